// round 10
// baseline (speedup 1.0000x reference)
#include <cuda_runtime.h>

#define NIMG    64
#define CH      36
#define NCLS    32
#define ANCH    8400
#define NT      512
#define MAXDET  100
#define CONF_T  0.25f
#define IOU_T   0.45f
#define HB      8192          // histogram bins

typedef unsigned long long u64;

// ---------------- global scratch (static __device__: allowed) ----------------
__device__ u64    g_key[NIMG][ANCH];
__device__ float4 g_box[NIMG][ANCH];
__device__ float  g_area[NIMG][ANCH];
__device__ float  g_cls[NIMG][ANCH];

static __device__ __forceinline__ unsigned mapf(float f) {
    unsigned u = __float_as_uint(f);
    return (u & 0x80000000u) ? ~u : (u | 0x80000000u);
}
static __device__ __forceinline__ float unmapf(unsigned u) {
    return __uint_as_float((u & 0x80000000u) ? (u ^ 0x80000000u) : ~u);
}
// monotone score bin: mapped scores for best in [CONF,1.0) span
// [0xBE800000, 0xBF800000) = 2^24 codes -> 8192 uniform bins of 2^11 codes.
static __device__ __forceinline__ int keybin(u64 k) {
    unsigned hi = (unsigned)(k >> 32);
    unsigned d  = hi - 0xBE800000u;       // mapf(0.25f)
    int bn = (int)(d >> 11);
    return bn > (HB - 1) ? (HB - 1) : bn;
}

// exact-decision IoU > IOU_T test (guard-banded FMA, __fdiv_rn only in band)
static __device__ __forceinline__ bool sup_test(float4 w, float wa, float4 b, float ba) {
    float yy1 = fmaxf(w.x, b.x), xx1 = fmaxf(w.y, b.y);
    float yy2 = fminf(w.z, b.z), xx2 = fminf(w.w, b.w);
    float dy = fmaxf(__fsub_rn(yy2, yy1), 0.f);
    float dx = fmaxf(__fsub_rn(xx2, xx1), 0.f);
    float inter = __fmul_rn(dy, dx);
    float uni = __fsub_rn(__fadd_rn(wa, ba), inter);
    float t   = __fmaf_rn(-IOU_T, uni, inter);
    float bnd = 3e-7f * uni;
    if (t > bnd)  return true;
    if (t < -bnd) return false;
    return (uni > 0.f) && (__fdiv_rn(inter, uni) > IOU_T);
}

// ---------------- kernel 1: decode (bandwidth-bound, 256 CTAs) ----------------
__global__ __launch_bounds__(NT)
void decode_kernel(const float* __restrict__ in)
{
    const int img = blockIdx.y;
    const int chk = blockIdx.x;          // 4 chunks of 2100 anchors
    const float* base = in + (size_t)img * CH * ANCH;
    const int lo = chk * 2100;

    for (int a = lo + threadIdx.x; a < lo + 2100; a += NT) {
        float xc = base[a];
        float yc = base[ANCH + a];
        float w  = base[2 * ANCH + a];
        float h  = base[3 * ANCH + a];
        float best = base[4 * ANCH + a];
        int bc = 0;
        #pragma unroll
        for (int c = 1; c < NCLS; c++) {
            float v = base[(4 + c) * ANCH + a];
            if (v > best) { best = v; bc = c; }   // first-max == jnp.argmax
        }
        float y1 = fminf(fmaxf(yc - 0.5f * h, 0.f), 1.f);
        float x1 = fminf(fmaxf(xc - 0.5f * w, 0.f), 1.f);
        float y2 = fminf(fmaxf(yc + 0.5f * h, 0.f), 1.f);
        float x2 = fminf(fmaxf(xc + 0.5f * w, 0.f), 1.f);
        float area = __fmul_rn(__fsub_rn(y2, y1), __fsub_rn(x2, x1));
        u64 key = 0ull;
        if (best >= CONF_T)
            key = ((u64)mapf(best) << 32) | (unsigned)(0xFFFFFF - a);
        g_key[img][a]  = key;
        g_box[img][a]  = make_float4(y1, x1, y2, x2);
        g_area[img][a] = area;
        g_cls[img][a]  = (float)bc;
    }
}

// ---------------- kernel 2: counting-sort + chunked accept scan ----------------
// SMEM layout (bytes)
#define OFF_SKEY   0                       // u64[8400]  = 67200
#define OFF_SORT   67200                   // u64[8400]  = 67200
#define OFF_HIST   134400                  // u32[8192]  = 32768
#define OFF_OFFS   167168                  // u32[8192]  = 32768
#define OFF_SA     199936                  // u32[512]
#define OFF_SB     201984                  // u32[512]
#define OFF_CKEY   204032                  // u64[512]   = 4096
#define OFF_CBOX   208128                  // float4[512]= 8192
#define OFF_CAREA  216320                  // f32[512]   = 2048
#define OFF_ACCB   218368                  // float4[100]= 1600
#define OFF_ACCA   219968                  // f32[100]   = 400
#define OFF_ALV    220368                  // u32[16]    = 64
#define OFF_MISC   220432                  // u32[8]
#define SMEM_TOTAL 220480

__global__ __launch_bounds__(NT, 1)
void nms_kernel(float* __restrict__ out)
{
    extern __shared__ char smem[];
    u64*      skey  = (u64*)(smem + OFF_SKEY);
    u64*      ssort = (u64*)(smem + OFF_SORT);
    unsigned* hist  = (unsigned*)(smem + OFF_HIST);
    unsigned* offs  = (unsigned*)(smem + OFF_OFFS);
    unsigned* sA    = (unsigned*)(smem + OFF_SA);
    unsigned* sB    = (unsigned*)(smem + OFF_SB);
    u64*      ckey  = (u64*)(smem + OFF_CKEY);
    float4*   cbox  = (float4*)(smem + OFF_CBOX);
    float*    carea = (float*)(smem + OFF_CAREA);
    float4*   accb  = (float4*)(smem + OFF_ACCB);
    float*    acca  = (float*)(smem + OFF_ACCA);
    unsigned* alv   = (unsigned*)(smem + OFF_ALV);
    unsigned* misc  = (unsigned*)(smem + OFF_MISC);

    const int tid  = threadIdx.x;
    const int img  = blockIdx.x;
    const int wid  = tid >> 5;
    const int lane = tid & 31;

    float* boxes_out = out + (size_t)img * MAXDET * 4;
    float* cls_out   = out + (size_t)NIMG * MAXDET * 4 + (size_t)img * MAXDET;
    float* sco_out   = out + (size_t)NIMG * MAXDET * 5 + (size_t)img * MAXDET;
    float* nd_out    = out + (size_t)NIMG * MAXDET * 6 + img;

    // --- load keys to smem + histogram ---
    for (int i = tid; i < HB; i += NT) hist[i] = 0;
    if (tid == 0) misc[0] = 0;
    __syncthreads();
    for (int it = 0; it < 17; it++) {
        int i = tid + it * NT;
        if (i < ANCH) {
            u64 k = g_key[img][i];
            skey[i] = k;
            if (k) atomicAdd(&hist[keybin(k)], 1u);
        }
    }
    __syncthreads();

    // --- chunk sums + inclusive suffix scan over 512 chunks of 16 bins ---
    {
        unsigned s = 0;
        #pragma unroll
        for (int b = 0; b < 16; b++) s += hist[tid * 16 + b];
        sA[tid] = s;
    }
    __syncthreads();
    {
        unsigned* src = sA; unsigned* dst = sB;
        for (int off = 1; off < NT; off <<= 1) {
            unsigned v = src[tid] + ((tid + off < NT) ? src[tid + off] : 0u);
            __syncthreads();
            dst[tid] = v;
            __syncthreads();
            unsigned* t2 = src; src = dst; dst = t2;
        }
        if (src != sA) { sA[tid] = src[tid]; __syncthreads(); }
    }
    const int totalPos = (int)sA[0];

    // --- per-bin start offsets for DESCENDING order: offs[b] = #keys in bins > b ---
    {
        unsigned carry = (tid < NT - 1) ? sA[tid + 1] : 0u;
        for (int b = tid * 16 + 15; b >= tid * 16; b--) {
            offs[b] = carry;
            carry += hist[b];
        }
    }
    __syncthreads();

    // --- scatter into sorted array (within-bin order arbitrary for now) ---
    for (int it = 0; it < 17; it++) {
        int i = tid + it * NT;
        if (i < ANCH) {
            u64 k = skey[i];
            if (k) {
                unsigned pos = atomicAdd(&offs[keybin(k)], 1u);
                ssort[pos] = k;
            }
        }
    }
    __syncthreads();

    // --- within-bin fix: insertion-sort each multi-occupancy bin (desc u64) ---
    for (int b = tid; b < HB; b += NT) {
        unsigned cnt = hist[b];
        if (cnt > 1) {
            int st = (int)offs[b] - (int)cnt;   // offs[b] is now the segment end
            for (int x = st + 1; x < st + (int)cnt; x++) {
                u64 v = ssort[x];
                int y = x - 1;
                while (y >= st && ssort[y] < v) { ssort[y + 1] = ssort[y]; y--; }
                ssort[y + 1] = v;
            }
        }
    }
    __syncthreads();

    // --- chunked accept scan over the fully sorted candidate list ---
    int na = 0;
    for (int base = 0; base < totalPos && na < MAXDET; base += NT) {
        int j = base + tid;
        bool alivec = false;
        float4 cb = make_float4(0.f, 0.f, 0.f, 0.f);
        float  ca = 0.f;
        u64    k  = 0ull;
        if (j < totalPos) {
            k = ssort[j];
            int idx = 0xFFFFFF - (int)(unsigned)(k & 0xFFFFFFu);
            cb = g_box[img][idx];
            ca = g_area[img][idx];
            alivec = true;
            // pre-test vs all boxes accepted in earlier chunks (parallel, early break)
            for (int a2 = 0; a2 < na; a2++) {
                if (sup_test(accb[a2], acca[a2], cb, ca)) { alivec = false; break; }
            }
        }
        ckey[tid]  = k;
        cbox[tid]  = cb;
        carea[tid] = ca;
        unsigned wb_ = __ballot_sync(0xFFFFFFFFu, alivec);
        if (lane == 0) alv[wid] = wb_;
        __syncthreads();

        // --- warp 0: serial resolve within chunk (alive bits in lanes 0-15) ---
        if (wid == 0) {
            int lna = na;
            unsigned a32 = (lane < 16) ? alv[lane] : 0u;
            while (lna < MAXDET) {
                unsigned wm = __ballot_sync(0xFFFFFFFFu, a32 != 0u);
                if (!wm) break;
                int wf = __ffs(wm) - 1;                       // lowest word w/ alive
                unsigned aw = __shfl_sync(0xFFFFFFFFu, a32, wf);
                int lt = __ffs(aw) - 1;                       // lowest bit = earliest
                int ts = wf * 32 + lt;
                float4 wbx = cbox[ts];                        // broadcast LDS
                float  wav = carea[ts];
                if (lane == wf) {
                    u64 ck = ckey[ts];
                    int idx = 0xFFFFFF - (int)(unsigned)(ck & 0xFFFFFFu);
                    boxes_out[lna * 4 + 0] = wbx.x;
                    boxes_out[lna * 4 + 1] = wbx.y;
                    boxes_out[lna * 4 + 2] = wbx.z;
                    boxes_out[lna * 4 + 3] = wbx.w;
                    cls_out[lna] = g_cls[img][idx];
                    sco_out[lna] = unmapf((unsigned)(ck >> 32));
                    accb[lna] = wbx;
                    acca[lna] = wav;
                    a32 &= ~(1u << lt);                       // consume winner
                }
                // each lane suppresses only ITS still-alive candidates
                unsigned rem = a32;
                while (rem) {
                    int bb = __ffs(rem) - 1;
                    rem &= rem - 1;
                    int t2 = lane * 32 + bb;
                    if (sup_test(wbx, wav, cbox[t2], carea[t2]))
                        a32 &= ~(1u << bb);
                }
                lna++;
            }
            if (lane == 0) misc[0] = (unsigned)lna;
        }
        __syncthreads();
        na = (int)misc[0];
    }

    // --- pad remaining outputs with zeros; write num_det ---
    for (int t = na * 4 + tid; t < MAXDET * 4; t += NT) boxes_out[t] = 0.f;
    for (int t = na + tid; t < MAXDET; t += NT) { cls_out[t] = 0.f; sco_out[t] = 0.f; }
    if (tid == 0) *nd_out = (float)na;
}

extern "C" void kernel_launch(void* const* d_in, const int* in_sizes, int n_in,
                              void* d_out, int out_size)
{
    (void)in_sizes; (void)n_in; (void)out_size;
    const float* in = (const float*)d_in[0];
    float* out = (float*)d_out;
    cudaFuncSetAttribute(nms_kernel,
                         cudaFuncAttributeMaxDynamicSharedMemorySize, SMEM_TOTAL);
    decode_kernel<<<dim3(4, NIMG), NT>>>(in);
    nms_kernel<<<NIMG, NT, SMEM_TOTAL>>>(out);
}

// round 11
// speedup vs baseline: 1.1836x; 1.1836x over previous
#include <cuda_runtime.h>

#define NIMG    64
#define CH      36
#define NCLS    32
#define ANCH    8400
#define NT      512
#define MAXDET  100
#define CONF_T  0.25f
#define IOU_T   0.45f
#define WCAP    512           // candidate window capacity (1 per thread)
#define HB      8192          // histogram bins

typedef unsigned long long u64;

// ---------------- global scratch (static __device__: allowed) ----------------
__device__ u64    g_key[NIMG][ANCH];
__device__ float4 g_box[NIMG][ANCH];
__device__ float  g_area[NIMG][ANCH];
__device__ float  g_cls[NIMG][ANCH];

static __device__ __forceinline__ unsigned mapf(float f) {
    unsigned u = __float_as_uint(f);
    return (u & 0x80000000u) ? ~u : (u | 0x80000000u);
}
static __device__ __forceinline__ float unmapf(unsigned u) {
    return __uint_as_float((u & 0x80000000u) ? (u ^ 0x80000000u) : ~u);
}
// monotone score bin: mapped scores for best in [CONF,1.0) span
// [0xBE800000, 0xBF800000) = 2^24 codes -> 8192 uniform bins of 2^11 codes.
static __device__ __forceinline__ int keybin(u64 k) {
    unsigned hi = (unsigned)(k >> 32);
    unsigned d  = hi - 0xBE800000u;       // mapf(0.25f)
    int bn = (int)(d >> 11);
    return bn > (HB - 1) ? (HB - 1) : bn;
}

// exact-decision IoU > IOU_T test (guard-banded FMA, __fdiv_rn only in band)
static __device__ __forceinline__ bool sup_test(float4 w, float wa, float4 b, float ba) {
    float yy1 = fmaxf(w.x, b.x), xx1 = fmaxf(w.y, b.y);
    float yy2 = fminf(w.z, b.z), xx2 = fminf(w.w, b.w);
    float dy = fmaxf(__fsub_rn(yy2, yy1), 0.f);
    float dx = fmaxf(__fsub_rn(xx2, xx1), 0.f);
    float inter = __fmul_rn(dy, dx);
    float uni = __fsub_rn(__fadd_rn(wa, ba), inter);
    float t   = __fmaf_rn(-IOU_T, uni, inter);
    float bnd = 3e-7f * uni;
    if (t > bnd)  return true;
    if (t < -bnd) return false;
    return (uni > 0.f) && (__fdiv_rn(inter, uni) > IOU_T);
}

// ---------------- kernel 1: decode (bandwidth-bound, 256 CTAs) ----------------
__global__ __launch_bounds__(NT)
void decode_kernel(const float* __restrict__ in)
{
    const int img = blockIdx.y;
    const int chk = blockIdx.x;          // 4 chunks of 2100 anchors
    const float* base = in + (size_t)img * CH * ANCH;
    const int lo = chk * 2100;

    for (int a = lo + threadIdx.x; a < lo + 2100; a += NT) {
        float xc = base[a];
        float yc = base[ANCH + a];
        float w  = base[2 * ANCH + a];
        float h  = base[3 * ANCH + a];
        float best = base[4 * ANCH + a];
        int bc = 0;
        #pragma unroll
        for (int c = 1; c < NCLS; c++) {
            float v = base[(4 + c) * ANCH + a];
            if (v > best) { best = v; bc = c; }   // first-max == jnp.argmax
        }
        float y1 = fminf(fmaxf(yc - 0.5f * h, 0.f), 1.f);
        float x1 = fminf(fmaxf(xc - 0.5f * w, 0.f), 1.f);
        float y2 = fminf(fmaxf(yc + 0.5f * h, 0.f), 1.f);
        float x2 = fminf(fmaxf(xc + 0.5f * w, 0.f), 1.f);
        float area = __fmul_rn(__fsub_rn(y2, y1), __fsub_rn(x2, x1));
        u64 key = 0ull;
        if (best >= CONF_T)
            key = ((u64)mapf(best) << 32) | (unsigned)(0xFFFFFF - a);
        g_key[img][a]  = key;
        g_box[img][a]  = make_float4(y1, x1, y2, x2);
        g_area[img][a] = area;
        g_cls[img][a]  = (float)bc;
    }
}

// ---------------- kernel 2: windowed sort + parallel-pretest NMS ----------------
// SMEM layout (bytes)
#define OFF_SKEY   0                       // u64[8400]  = 67200
#define OFF_HIST   67200                   // u32[8192]  = 32768
#define OFF_SA     99968                   // u32[512]
#define OFF_SB     102016                  // u32[512]
#define OFF_CKEY   104064                  // u64[512]   = 4096
#define OFF_CBOX   108160                  // float4[512]= 8192
#define OFF_CAREA  116352                  // f32[512]
#define OFF_CCLS   118400                  // f32[512]
#define OFF_ACCB   120448                  // float4[100]= 1600
#define OFF_ACCA   122048                  // f32[100]   = 400
#define OFF_ALV    122448                  // u32[16]    = 64
#define OFF_MISC   122512                  // u32[12]
#define SMEM_TOTAL 122560

__global__ __launch_bounds__(NT, 1)
void nms_kernel(float* __restrict__ out)
{
    extern __shared__ char smem[];
    u64*      skey  = (u64*)(smem + OFF_SKEY);
    unsigned* hist  = (unsigned*)(smem + OFF_HIST);
    unsigned* sA    = (unsigned*)(smem + OFF_SA);
    unsigned* sB    = (unsigned*)(smem + OFF_SB);
    u64*      ckey  = (u64*)(smem + OFF_CKEY);
    float4*   cbox  = (float4*)(smem + OFF_CBOX);
    float*    carea = (float*)(smem + OFF_CAREA);
    float*    ccls  = (float*)(smem + OFF_CCLS);
    float4*   accb  = (float4*)(smem + OFF_ACCB);
    float*    acca  = (float*)(smem + OFF_ACCA);
    unsigned* alv   = (unsigned*)(smem + OFF_ALV);
    unsigned* misc  = (unsigned*)(smem + OFF_MISC);

    const int tid  = threadIdx.x;
    const int img  = blockIdx.x;
    const int wid  = tid >> 5;
    const int lane = tid & 31;

    float* boxes_out = out + (size_t)img * MAXDET * 4;
    float* cls_out   = out + (size_t)NIMG * MAXDET * 4 + (size_t)img * MAXDET;
    float* sco_out   = out + (size_t)NIMG * MAXDET * 5 + (size_t)img * MAXDET;
    float* nd_out    = out + (size_t)NIMG * MAXDET * 6 + img;

    // --- load keys to smem + histogram ---
    for (int i = tid; i < HB; i += NT) hist[i] = 0;
    if (tid == 0) misc[3] = 0;   // accepted count
    __syncthreads();
    for (int it = 0; it < 17; it++) {
        int i = tid + it * NT;
        if (i < ANCH) {
            u64 k = g_key[img][i];
            skey[i] = k;
            if (k) atomicAdd(&hist[keybin(k)], 1u);
        }
    }
    __syncthreads();

    // --- chunk sums + inclusive suffix scan over 512 chunks ---
    {
        unsigned s = 0;
        #pragma unroll
        for (int b = 0; b < 16; b++) s += hist[tid * 16 + b];
        sA[tid] = s;
    }
    __syncthreads();
    {
        unsigned* src = sA; unsigned* dst = sB;
        for (int off = 1; off < NT; off <<= 1) {
            unsigned v = src[tid] + ((tid + off < NT) ? src[tid + off] : 0u);
            __syncthreads();
            dst[tid] = v;
            __syncthreads();
            unsigned* t2 = src; src = dst; dst = t2;
        }
        if (src != sA) { sA[tid] = src[tid]; __syncthreads(); }
    }
    const unsigned totalPos = sA[0];

    int na = 0;
    unsigned cumHi = 0;
    int hi = HB;

    while (na < MAXDET && cumHi < totalPos) {
        // --- find lo: min bin with cumAbove(bin)-cumHi <= WCAP ---
        if (tid == 0) { misc[0] = 0; misc[1] = 0xFFFFFFFFu; misc[2] = 0; }
        __syncthreads();
        int mylo = -1; unsigned myloCum = 0;
        {
            unsigned carry = (tid < NT - 1) ? sA[tid + 1] : 0u;
            for (int b = tid * 16 + 15; b >= tid * 16; b--) {
                carry += hist[b];
                if (b < hi && (carry - cumHi) <= WCAP) { mylo = b; myloCum = carry; }
            }
        }
        if (mylo >= 0) atomicMin(&misc[1], (unsigned)mylo);
        __syncthreads();
        int lo = (int)misc[1];
        if (lo == (int)0xFFFFFFFF) {            // pathological fat bin: clamp
            lo = hi - 1;
            if (tid == 0) misc[2] = cumHi + hist[lo];
        } else if (mylo == lo) {
            misc[2] = myloCum;
        }
        __syncthreads();
        unsigned loCum = misc[2];

        // --- select window [lo, hi) into ckey (unordered) ---
        for (int it = 0; it < 17; it++) {
            int i = tid + it * NT;
            u64 k = (i < ANCH) ? skey[i] : 0ull;
            bool cond = false;
            if (k) { int bn = keybin(k); cond = (bn >= lo && bn < hi); }
            unsigned act = __ballot_sync(0xFFFFFFFFu, cond);
            unsigned basep = 0;
            int leader = act ? (__ffs(act) - 1) : 0;
            if (act && lane == leader) basep = atomicAdd(&misc[0], __popc(act));
            basep = __shfl_sync(0xFFFFFFFFu, basep, leader);
            if (cond) {
                unsigned pos = basep + __popc(act & ((1u << lane) - 1));
                if (pos < WCAP) ckey[pos] = k;
            }
        }
        __syncthreads();
        int selCount = (int)misc[0]; if (selCount > WCAP) selCount = WCAP;

        if (selCount > 0) {
            // --- bitonic sort, 1 key/thread, descending; shuffles for j<32 ---
            u64 v = (tid < selCount) ? ckey[tid] : 0ull;
            __syncthreads();   // ckey reused as exchange buffer
            #pragma unroll
            for (int k = 2; k <= NT; k <<= 1) {
                for (int j = k >> 1; j > 0; j >>= 1) {
                    u64 o;
                    if (j >= 32) {
                        ckey[tid] = v;
                        __syncthreads();
                        o = ckey[tid ^ j];
                        __syncthreads();
                    } else {
                        o = __shfl_xor_sync(0xFFFFFFFFu, v, j);
                    }
                    bool dirDesc = ((tid & k) == 0);
                    bool lower   = ((tid & j) == 0);
                    bool takeMax = (dirDesc == lower);
                    v = takeMax ? (v > o ? v : o) : (v < o ? v : o);
                }
            }
            ckey[tid] = v;

            // --- gather box for my sorted candidate + PARALLEL pre-test vs accepted ---
            bool alivec = false;
            if (tid < selCount) {
                int idx = 0xFFFFFF - (int)(unsigned)(v & 0xFFFFFFu);
                float4 cb = g_box[img][idx];
                float  ca = g_area[img][idx];
                cbox[tid]  = cb;
                carea[tid] = ca;
                ccls[tid]  = g_cls[img][idx];
                alivec = true;
                for (int a2 = 0; a2 < na; a2++) {
                    if (sup_test(accb[a2], acca[a2], cb, ca)) { alivec = false; break; }
                }
            }
            unsigned wb_ = __ballot_sync(0xFFFFFFFFu, alivec);
            if (lane == 0) alv[wid] = wb_;
            __syncthreads();

            // --- warp 0: serial resolve over alive bits (lanes 0-15 hold mask) ---
            if (wid == 0) {
                int lna = na;
                unsigned a32 = (lane < 16) ? alv[lane] : 0u;
                while (lna < MAXDET) {
                    unsigned wm = __ballot_sync(0xFFFFFFFFu, a32 != 0u);
                    if (!wm) break;
                    int wf = __ffs(wm) - 1;                   // earliest 32-block
                    unsigned aw = __shfl_sync(0xFFFFFFFFu, a32, wf);
                    int lt = __ffs(aw) - 1;                   // earliest in block
                    int ts = wf * 32 + lt;
                    float4 wbx = cbox[ts];                    // broadcast LDS
                    float  wav = carea[ts];
                    if (lane == wf) {
                        u64 ck = ckey[ts];
                        boxes_out[lna * 4 + 0] = wbx.x;
                        boxes_out[lna * 4 + 1] = wbx.y;
                        boxes_out[lna * 4 + 2] = wbx.z;
                        boxes_out[lna * 4 + 3] = wbx.w;
                        cls_out[lna] = ccls[ts];
                        sco_out[lna] = unmapf((unsigned)(ck >> 32));
                        accb[lna] = wbx;
                        acca[lna] = wav;
                        a32 &= ~(1u << lt);                   // consume winner
                    }
                    // each lane suppresses only ITS still-alive candidates
                    unsigned rem = a32;
                    while (rem) {
                        int bb = __ffs(rem) - 1;
                        rem &= rem - 1;
                        int t2 = lane * 32 + bb;
                        if (sup_test(wbx, wav, cbox[t2], carea[t2]))
                            a32 &= ~(1u << bb);
                    }
                    lna++;
                }
                if (lane == 0) misc[3] = (unsigned)lna;
            }
            __syncthreads();
            na = (int)misc[3];
        }
        hi = lo;
        cumHi = loCum;
    }

    // --- pad remaining outputs with zeros; write num_det ---
    for (int t = na * 4 + tid; t < MAXDET * 4; t += NT) boxes_out[t] = 0.f;
    for (int t = na + tid; t < MAXDET; t += NT) { cls_out[t] = 0.f; sco_out[t] = 0.f; }
    if (tid == 0) *nd_out = (float)na;
}

extern "C" void kernel_launch(void* const* d_in, const int* in_sizes, int n_in,
                              void* d_out, int out_size)
{
    (void)in_sizes; (void)n_in; (void)out_size;
    const float* in = (const float*)d_in[0];
    float* out = (float*)d_out;
    cudaFuncSetAttribute(nms_kernel,
                         cudaFuncAttributeMaxDynamicSharedMemorySize, SMEM_TOTAL);
    decode_kernel<<<dim3(4, NIMG), NT>>>(in);
    nms_kernel<<<NIMG, NT, SMEM_TOTAL>>>(out);
}

// round 13
// speedup vs baseline: 5.3802x; 4.5458x over previous
#include <cuda_runtime.h>

#define NIMG    64
#define CH      36
#define NCLS    32
#define ANCH    8400
#define NT      512
#define MAXDET  100
#define CONF_T  0.25f
#define IOU_T   0.45f
#define WCAP    512           // candidate window capacity (1 per thread)
#define HB      8192          // histogram bins

typedef unsigned long long u64;

// ---------------- global scratch (static __device__: allowed) ----------------
__device__ u64    g_key[NIMG][ANCH];
__device__ float4 g_box[NIMG][ANCH];
__device__ float  g_area[NIMG][ANCH];
__device__ float  g_cls[NIMG][ANCH];

static __device__ __forceinline__ unsigned mapf(float f) {
    unsigned u = __float_as_uint(f);
    return (u & 0x80000000u) ? ~u : (u | 0x80000000u);
}
static __device__ __forceinline__ float unmapf(unsigned u) {
    return __uint_as_float((u & 0x80000000u) ? (u ^ 0x80000000u) : ~u);
}
// monotone score bin: mapped scores for best in [CONF,1.0) span
// [0xBE800000, 0xBF800000) = 2^24 codes -> 8192 uniform bins of 2^11 codes.
static __device__ __forceinline__ int keybin(u64 k) {
    unsigned hi = (unsigned)(k >> 32);
    unsigned d  = hi - 0xBE800000u;       // mapf(0.25f)
    int bn = (int)(d >> 11);
    return bn > (HB - 1) ? (HB - 1) : bn;
}

// exact-decision IoU > IOU_T test (guard-banded FMA, __fdiv_rn only in band)
static __device__ __forceinline__ bool sup_test(float4 w, float wa, float4 b, float ba) {
    float yy1 = fmaxf(w.x, b.x), xx1 = fmaxf(w.y, b.y);
    float yy2 = fminf(w.z, b.z), xx2 = fminf(w.w, b.w);
    float dy = fmaxf(__fsub_rn(yy2, yy1), 0.f);
    float dx = fmaxf(__fsub_rn(xx2, xx1), 0.f);
    float inter = __fmul_rn(dy, dx);
    float uni = __fsub_rn(__fadd_rn(wa, ba), inter);
    float t   = __fmaf_rn(-IOU_T, uni, inter);
    float bnd = 3e-7f * uni;
    if (t > bnd)  return true;
    if (t < -bnd) return false;
    return (uni > 0.f) && (__fdiv_rn(inter, uni) > IOU_T);
}

// ---------------- kernel 1: decode (bandwidth-bound, 256 CTAs) ----------------
__global__ __launch_bounds__(NT)
void decode_kernel(const float* __restrict__ in)
{
    const int img = blockIdx.y;
    const int chk = blockIdx.x;          // 4 chunks of 2100 anchors
    const float* base = in + (size_t)img * CH * ANCH;
    const int lo = chk * 2100;

    for (int a = lo + threadIdx.x; a < lo + 2100; a += NT) {
        float xc = base[a];
        float yc = base[ANCH + a];
        float w  = base[2 * ANCH + a];
        float h  = base[3 * ANCH + a];
        float best = base[4 * ANCH + a];
        int bc = 0;
        #pragma unroll
        for (int c = 1; c < NCLS; c++) {
            float v = base[(4 + c) * ANCH + a];
            if (v > best) { best = v; bc = c; }   // first-max == jnp.argmax
        }
        float y1 = fminf(fmaxf(yc - 0.5f * h, 0.f), 1.f);
        float x1 = fminf(fmaxf(xc - 0.5f * w, 0.f), 1.f);
        float y2 = fminf(fmaxf(yc + 0.5f * h, 0.f), 1.f);
        float x2 = fminf(fmaxf(xc + 0.5f * w, 0.f), 1.f);
        float area = __fmul_rn(__fsub_rn(y2, y1), __fsub_rn(x2, x1));
        u64 key = 0ull;
        if (best >= CONF_T)
            key = ((u64)mapf(best) << 32) | (unsigned)(0xFFFFFF - a);
        g_key[img][a]  = key;
        g_box[img][a]  = make_float4(y1, x1, y2, x2);
        g_area[img][a] = area;
        g_cls[img][a]  = (float)bc;
    }
}

// ---------------- kernel 2: windowed sort + block-parallel accept stepping ----
// SMEM layout (bytes)
#define OFF_SKEY   0                       // u64[8400]  = 67200
#define OFF_HIST   67200                   // u32[8192]  = 32768
#define OFF_SA     99968                   // u32[512]
#define OFF_SB     102016                  // u32[512]
#define OFF_CKEY   104064                  // u64[512]   = 4096
#define OFF_CBOX   108160                  // float4[512]= 8192
#define OFF_CAREA  116352                  // f32[512]
#define OFF_CCLS   118400                  // f32[512]
#define OFF_ACCB   120448                  // float4[100]= 1600
#define OFF_ACCA   122048                  // f32[100]   = 400
#define OFF_ALV    122448                  // u32[2][16] = 128
#define OFF_MISC   122576                  // u32[12]
#define SMEM_TOTAL 122624

__global__ __launch_bounds__(NT, 1)
void nms_kernel(float* __restrict__ out)
{
    extern __shared__ char smem[];
    u64*      skey  = (u64*)(smem + OFF_SKEY);
    unsigned* hist  = (unsigned*)(smem + OFF_HIST);
    unsigned* sA    = (unsigned*)(smem + OFF_SA);
    unsigned* sB    = (unsigned*)(smem + OFF_SB);
    u64*      ckey  = (u64*)(smem + OFF_CKEY);
    float4*   cbox  = (float4*)(smem + OFF_CBOX);
    float*    carea = (float*)(smem + OFF_CAREA);
    float*    ccls  = (float*)(smem + OFF_CCLS);
    float4*   accb  = (float4*)(smem + OFF_ACCB);
    float*    acca  = (float*)(smem + OFF_ACCA);
    unsigned* alv   = (unsigned*)(smem + OFF_ALV);
    unsigned* misc  = (unsigned*)(smem + OFF_MISC);

    const int tid  = threadIdx.x;
    const int img  = blockIdx.x;
    const int wid  = tid >> 5;
    const int lane = tid & 31;

    float* boxes_out = out + (size_t)img * MAXDET * 4;
    float* cls_out   = out + (size_t)NIMG * MAXDET * 4 + (size_t)img * MAXDET;
    float* sco_out   = out + (size_t)NIMG * MAXDET * 5 + (size_t)img * MAXDET;
    float* nd_out    = out + (size_t)NIMG * MAXDET * 6 + img;

    // --- load keys to smem + histogram ---
    for (int i = tid; i < HB; i += NT) hist[i] = 0;
    __syncthreads();
    for (int it = 0; it < 17; it++) {
        int i = tid + it * NT;
        if (i < ANCH) {
            u64 k = g_key[img][i];
            skey[i] = k;
            if (k) atomicAdd(&hist[keybin(k)], 1u);
        }
    }
    __syncthreads();

    // --- chunk sums + inclusive suffix scan over 512 chunks ---
    {
        unsigned s = 0;
        #pragma unroll
        for (int b = 0; b < 16; b++) s += hist[tid * 16 + b];
        sA[tid] = s;
    }
    __syncthreads();
    {
        unsigned* src = sA; unsigned* dst = sB;
        for (int off = 1; off < NT; off <<= 1) {
            unsigned v = src[tid] + ((tid + off < NT) ? src[tid + off] : 0u);
            __syncthreads();
            dst[tid] = v;
            __syncthreads();
            unsigned* t2 = src; src = dst; dst = t2;
        }
        if (src != sA) { sA[tid] = src[tid]; __syncthreads(); }
    }
    const unsigned totalPos = sA[0];

    int na = 0;
    unsigned cumHi = 0;
    int hi = HB;
    int it2 = 0;          // step-loop parity counter (global across windows)

    while (na < MAXDET && cumHi < totalPos) {
        // --- find lo: min bin with cumAbove(bin)-cumHi <= WCAP ---
        if (tid == 0) { misc[0] = 0; misc[1] = 0xFFFFFFFFu; misc[2] = 0; }
        __syncthreads();
        int mylo = -1; unsigned myloCum = 0;
        {
            unsigned carry = (tid < NT - 1) ? sA[tid + 1] : 0u;
            for (int b = tid * 16 + 15; b >= tid * 16; b--) {
                carry += hist[b];
                if (b < hi && (carry - cumHi) <= WCAP) { mylo = b; myloCum = carry; }
            }
        }
        if (mylo >= 0) atomicMin(&misc[1], (unsigned)mylo);
        __syncthreads();
        int lo = (int)misc[1];
        if (lo == (int)0xFFFFFFFF) {            // pathological fat bin: clamp
            lo = hi - 1;
            if (tid == 0) misc[2] = cumHi + hist[lo];
        } else if (mylo == lo) {
            misc[2] = myloCum;
        }
        __syncthreads();
        unsigned loCum = misc[2];

        // --- select window [lo, hi) into ckey (unordered) ---
        for (int it = 0; it < 17; it++) {
            int i = tid + it * NT;
            u64 k = (i < ANCH) ? skey[i] : 0ull;
            bool cond = false;
            if (k) { int bn = keybin(k); cond = (bn >= lo && bn < hi); }
            unsigned act = __ballot_sync(0xFFFFFFFFu, cond);
            unsigned basep = 0;
            int leader = act ? (__ffs(act) - 1) : 0;
            if (act && lane == leader) basep = atomicAdd(&misc[0], __popc(act));
            basep = __shfl_sync(0xFFFFFFFFu, basep, leader);
            if (cond) {
                unsigned pos = basep + __popc(act & ((1u << lane) - 1));
                if (pos < WCAP) ckey[pos] = k;
            }
        }
        __syncthreads();
        int selCount = (int)misc[0]; if (selCount > WCAP) selCount = WCAP;

        if (selCount > 0) {
            // --- bitonic sort, 1 key/thread, descending; shuffles for j<32 ---
            u64 v = (tid < selCount) ? ckey[tid] : 0ull;
            __syncthreads();   // ckey reused as exchange buffer
            #pragma unroll
            for (int k = 2; k <= NT; k <<= 1) {
                for (int j = k >> 1; j > 0; j >>= 1) {
                    u64 o;
                    if (j >= 32) {
                        ckey[tid] = v;
                        __syncthreads();
                        o = ckey[tid ^ j];
                        __syncthreads();
                    } else {
                        o = __shfl_xor_sync(0xFFFFFFFFu, v, j);
                    }
                    bool dirDesc = ((tid & k) == 0);
                    bool lower   = ((tid & j) == 0);
                    bool takeMax = (dirDesc == lower);
                    v = takeMax ? (v > o ? v : o) : (v < o ? v : o);
                }
            }
            ckey[tid] = v;

            // --- gather box (registers + smem) + PARALLEL pre-test vs accepted ---
            float4 mycb = make_float4(0.f, 0.f, 0.f, 0.f);
            float  myca = 0.f;
            bool alivec = false;
            if (tid < selCount) {
                int idx = 0xFFFFFF - (int)(unsigned)(v & 0xFFFFFFu);
                mycb = g_box[img][idx];
                myca = g_area[img][idx];
                cbox[tid]  = mycb;
                carea[tid] = myca;
                ccls[tid]  = g_cls[img][idx];
                alivec = true;
                for (int a2 = 0; a2 < na; a2++) {
                    if (sup_test(accb[a2], acca[a2], mycb, myca)) { alivec = false; break; }
                }
            }

            // --- block-parallel accept stepping: first alive = next winner ---
            while (na < MAXDET) {
                int p = (it2 & 1) * 16; it2++;
                unsigned wb_ = __ballot_sync(0xFFFFFFFFu, alivec);
                if (lane == 0) alv[p + wid] = wb_;
                __syncthreads();      // orders alv (and cbox gather / accb) for all

                int ts = -1;
                #pragma unroll
                for (int w2 = 0; w2 < 16; w2++) {
                    unsigned x = alv[p + w2];
                    if (x) { ts = w2 * 32 + (__ffs(x) - 1); break; }
                }
                if (ts < 0) break;    // window exhausted (uniform decision)

                float4 wbx = cbox[ts];     // broadcast LDS
                float  wav = carea[ts];
                if (tid == ts) {
                    boxes_out[na * 4 + 0] = wbx.x;
                    boxes_out[na * 4 + 1] = wbx.y;
                    boxes_out[na * 4 + 2] = wbx.z;
                    boxes_out[na * 4 + 3] = wbx.w;
                    cls_out[na] = ccls[ts];
                    sco_out[na] = unmapf((unsigned)(ckey[ts] >> 32));
                    accb[na] = wbx;
                    acca[na] = wav;
                    alivec = false;        // winner consumed
                } else if (alivec) {
                    if (sup_test(wbx, wav, mycb, myca)) alivec = false;  // registers
                }
                na++;
            }
        }
        hi = lo;
        cumHi = loCum;
    }

    // --- pad remaining outputs with zeros; write num_det ---
    for (int t = na * 4 + tid; t < MAXDET * 4; t += NT) boxes_out[t] = 0.f;
    for (int t = na + tid; t < MAXDET; t += NT) { cls_out[t] = 0.f; sco_out[t] = 0.f; }
    if (tid == 0) *nd_out = (float)na;
}

extern "C" void kernel_launch(void* const* d_in, const int* in_sizes, int n_in,
                              void* d_out, int out_size)
{
    (void)in_sizes; (void)n_in; (void)out_size;
    const float* in = (const float*)d_in[0];
    float* out = (float*)d_out;
    cudaFuncSetAttribute(nms_kernel,
                         cudaFuncAttributeMaxDynamicSharedMemorySize, SMEM_TOTAL);
    decode_kernel<<<dim3(4, NIMG), NT>>>(in);
    nms_kernel<<<NIMG, NT, SMEM_TOTAL>>>(out);
}

// round 14
// speedup vs baseline: 5.7554x; 1.0697x over previous
#include <cuda_runtime.h>

#define NIMG    64
#define CH      36
#define NCLS    32
#define ANCH    8400
#define NT      512
#define MAXDET  100
#define CONF_T  0.25f
#define IOU_T   0.45f
#define WCAP    512           // candidate window capacity (1 per thread)
#define HB      8192          // histogram bins

typedef unsigned long long u64;

// ---------------- global scratch (static __device__: allowed) ----------------
__device__ u64    g_key[NIMG][ANCH];
__device__ float4 g_box[NIMG][ANCH];
__device__ float  g_area[NIMG][ANCH];
__device__ float  g_cls[NIMG][ANCH];

static __device__ __forceinline__ unsigned mapf(float f) {
    unsigned u = __float_as_uint(f);
    return (u & 0x80000000u) ? ~u : (u | 0x80000000u);
}
static __device__ __forceinline__ float unmapf(unsigned u) {
    return __uint_as_float((u & 0x80000000u) ? (u ^ 0x80000000u) : ~u);
}
// monotone score bin: mapped scores for best in [CONF,1.0) span
// [0xBE800000, 0xBF800000) = 2^24 codes -> 8192 uniform bins of 2^11 codes.
static __device__ __forceinline__ int keybin(u64 k) {
    unsigned hi = (unsigned)(k >> 32);
    unsigned d  = hi - 0xBE800000u;       // mapf(0.25f)
    int bn = (int)(d >> 11);
    return bn > (HB - 1) ? (HB - 1) : bn;
}

// exact-decision IoU > IOU_T test (guard-banded FMA, __fdiv_rn only in band)
static __device__ __forceinline__ bool sup_test(float4 w, float wa, float4 b, float ba) {
    float yy1 = fmaxf(w.x, b.x), xx1 = fmaxf(w.y, b.y);
    float yy2 = fminf(w.z, b.z), xx2 = fminf(w.w, b.w);
    float dy = fmaxf(__fsub_rn(yy2, yy1), 0.f);
    float dx = fmaxf(__fsub_rn(xx2, xx1), 0.f);
    float inter = __fmul_rn(dy, dx);
    float uni = __fsub_rn(__fadd_rn(wa, ba), inter);
    float t   = __fmaf_rn(-IOU_T, uni, inter);
    float bnd = 3e-7f * uni;
    if (t > bnd)  return true;
    if (t < -bnd) return false;
    return (uni > 0.f) && (__fdiv_rn(inter, uni) > IOU_T);
}

// ---------------- kernel 1: decode (bandwidth-bound, 256 CTAs) ----------------
__global__ __launch_bounds__(NT)
void decode_kernel(const float* __restrict__ in)
{
    const int img = blockIdx.y;
    const int chk = blockIdx.x;          // 4 chunks of 2100 anchors
    const float* base = in + (size_t)img * CH * ANCH;
    const int lo = chk * 2100;

    for (int a = lo + threadIdx.x; a < lo + 2100; a += NT) {
        float xc = base[a];
        float yc = base[ANCH + a];
        float w  = base[2 * ANCH + a];
        float h  = base[3 * ANCH + a];
        float best = base[4 * ANCH + a];
        int bc = 0;
        #pragma unroll
        for (int c = 1; c < NCLS; c++) {
            float v = base[(4 + c) * ANCH + a];
            if (v > best) { best = v; bc = c; }   // first-max == jnp.argmax
        }
        float y1 = fminf(fmaxf(yc - 0.5f * h, 0.f), 1.f);
        float x1 = fminf(fmaxf(xc - 0.5f * w, 0.f), 1.f);
        float y2 = fminf(fmaxf(yc + 0.5f * h, 0.f), 1.f);
        float x2 = fminf(fmaxf(xc + 0.5f * w, 0.f), 1.f);
        float area = __fmul_rn(__fsub_rn(y2, y1), __fsub_rn(x2, x1));
        u64 key = 0ull;
        if (best >= CONF_T)
            key = ((u64)mapf(best) << 32) | (unsigned)(0xFFFFFF - a);
        g_key[img][a]  = key;
        g_box[img][a]  = make_float4(y1, x1, y2, x2);
        g_area[img][a] = area;
        g_cls[img][a]  = (float)bc;
    }
}

// ---------------- kernel 2: bucket-scatter + sliced windows + stepping --------
// SMEM layout (bytes)
#define OFF_SKEY   0                       // u64[8400]  = 67200
#define OFF_SORT   67200                   // u64[8400]  = 67200
#define OFF_HIST   134400                  // u32[8192]  = 32768
#define OFF_OFFS   167168                  // u32[8192]  = 32768
#define OFF_SA     199936                  // u32[512]
#define OFF_SB     201984                  // u32[512]
#define OFF_CKEY   204032                  // u64[512]   = 4096
#define OFF_CBOX   208128                  // float4[512]= 8192
#define OFF_CAREA  216320                  // f32[512]
#define OFF_CCLS   218368                  // f32[512]
#define OFF_ACCB   220416                  // float4[100]= 1600
#define OFF_ACCA   222016                  // f32[100]   = 400
#define OFF_ALV    222416                  // u32[2][16] = 128
#define OFF_MISC   222544                  // u32[12]
#define SMEM_TOTAL 222592

__global__ __launch_bounds__(NT, 1)
void nms_kernel(float* __restrict__ out)
{
    extern __shared__ char smem[];
    u64*      skey  = (u64*)(smem + OFF_SKEY);
    u64*      ssort = (u64*)(smem + OFF_SORT);
    unsigned* hist  = (unsigned*)(smem + OFF_HIST);
    unsigned* offs  = (unsigned*)(smem + OFF_OFFS);
    unsigned* sA    = (unsigned*)(smem + OFF_SA);
    unsigned* sB    = (unsigned*)(smem + OFF_SB);
    u64*      ckey  = (u64*)(smem + OFF_CKEY);
    float4*   cbox  = (float4*)(smem + OFF_CBOX);
    float*    carea = (float*)(smem + OFF_CAREA);
    float*    ccls  = (float*)(smem + OFF_CCLS);
    float4*   accb  = (float4*)(smem + OFF_ACCB);
    float*    acca  = (float*)(smem + OFF_ACCA);
    unsigned* alv   = (unsigned*)(smem + OFF_ALV);
    unsigned* misc  = (unsigned*)(smem + OFF_MISC);

    const int tid  = threadIdx.x;
    const int img  = blockIdx.x;
    const int wid  = tid >> 5;
    const int lane = tid & 31;

    float* boxes_out = out + (size_t)img * MAXDET * 4;
    float* cls_out   = out + (size_t)NIMG * MAXDET * 4 + (size_t)img * MAXDET;
    float* sco_out   = out + (size_t)NIMG * MAXDET * 5 + (size_t)img * MAXDET;
    float* nd_out    = out + (size_t)NIMG * MAXDET * 6 + img;

    // --- load keys to smem + histogram ---
    for (int i = tid; i < HB; i += NT) hist[i] = 0;
    __syncthreads();
    for (int it = 0; it < 17; it++) {
        int i = tid + it * NT;
        if (i < ANCH) {
            u64 k = g_key[img][i];
            skey[i] = k;
            if (k) atomicAdd(&hist[keybin(k)], 1u);
        }
    }
    __syncthreads();

    // --- chunk sums + inclusive suffix scan over 512 chunks of 16 bins ---
    {
        unsigned s = 0;
        #pragma unroll
        for (int b = 0; b < 16; b++) s += hist[tid * 16 + b];
        sA[tid] = s;
    }
    __syncthreads();
    {
        unsigned* src = sA; unsigned* dst = sB;
        for (int off = 1; off < NT; off <<= 1) {
            unsigned v = src[tid] + ((tid + off < NT) ? src[tid + off] : 0u);
            __syncthreads();
            dst[tid] = v;
            __syncthreads();
            unsigned* t2 = src; src = dst; dst = t2;
        }
        if (src != sA) { sA[tid] = src[tid]; __syncthreads(); }
    }
    const unsigned totalPos = sA[0];

    // --- per-bin start offsets for DESCENDING bin order: offs[b] = #keys in bins > b ---
    {
        unsigned carry = (tid < NT - 1) ? sA[tid + 1] : 0u;
        for (int b = tid * 16 + 15; b >= tid * 16; b--) {
            offs[b] = carry;
            carry += hist[b];
        }
    }
    __syncthreads();

    // --- bucket scatter (NO within-bin order — window bitonic sort fixes it) ---
    for (int it = 0; it < 17; it++) {
        int i = tid + it * NT;
        if (i < ANCH) {
            u64 k = skey[i];
            if (k) ssort[atomicAdd(&offs[keybin(k)], 1u)] = k;
        }
    }
    __syncthreads();

    int na = 0;
    unsigned cumHi = 0;
    int hi = HB;
    int it2 = 0;          // step-loop parity counter (global across windows)

    while (na < MAXDET && cumHi < totalPos) {
        // --- find lo: min bin with cumAbove(bin)-cumHi <= WCAP ---
        if (tid == 0) { misc[1] = 0xFFFFFFFFu; misc[2] = 0; }
        __syncthreads();
        int mylo = -1; unsigned myloCum = 0;
        {
            unsigned carry = (tid < NT - 1) ? sA[tid + 1] : 0u;
            for (int b = tid * 16 + 15; b >= tid * 16; b--) {
                carry += hist[b];
                if (b < hi && (carry - cumHi) <= WCAP) { mylo = b; myloCum = carry; }
            }
        }
        if (mylo >= 0) atomicMin(&misc[1], (unsigned)mylo);
        __syncthreads();
        int lo = (int)misc[1];
        if (lo == (int)0xFFFFFFFF) {            // pathological fat bin: clamp
            lo = hi - 1;
            if (tid == 0) misc[2] = cumHi + hist[lo];
        } else if (mylo == lo) {
            misc[2] = myloCum;
        }
        __syncthreads();
        unsigned loCum = misc[2];

        // --- window = contiguous slice of the bucket-ordered array ---
        int selCount = (int)(loCum - cumHi);
        if (selCount > WCAP) selCount = WCAP;   // clamp envelope (fat bin only)

        if (selCount > 0) {
            u64 v = (tid < selCount) ? ssort[cumHi + tid] : 0ull;

            // --- bitonic sort, 1 key/thread, descending; shuffles for j<32 ---
            #pragma unroll
            for (int k = 2; k <= NT; k <<= 1) {
                for (int j = k >> 1; j > 0; j >>= 1) {
                    u64 o;
                    if (j >= 32) {
                        ckey[tid] = v;
                        __syncthreads();
                        o = ckey[tid ^ j];
                        __syncthreads();
                    } else {
                        o = __shfl_xor_sync(0xFFFFFFFFu, v, j);
                    }
                    bool dirDesc = ((tid & k) == 0);
                    bool lower   = ((tid & j) == 0);
                    bool takeMax = (dirDesc == lower);
                    v = takeMax ? (v > o ? v : o) : (v < o ? v : o);
                }
            }
            ckey[tid] = v;

            // --- gather box (registers + smem) + PARALLEL pre-test vs accepted ---
            float4 mycb = make_float4(0.f, 0.f, 0.f, 0.f);
            float  myca = 0.f;
            bool alivec = false;
            if (tid < selCount) {
                int idx = 0xFFFFFF - (int)(unsigned)(v & 0xFFFFFFu);
                mycb = g_box[img][idx];
                myca = g_area[img][idx];
                cbox[tid]  = mycb;
                carea[tid] = myca;
                ccls[tid]  = g_cls[img][idx];
                alivec = true;
                for (int a2 = 0; a2 < na; a2++) {
                    if (sup_test(accb[a2], acca[a2], mycb, myca)) { alivec = false; break; }
                }
            }

            // --- block-parallel accept stepping: first alive = next winner ---
            while (na < MAXDET) {
                int p = (it2 & 1) * 16; it2++;
                unsigned wb_ = __ballot_sync(0xFFFFFFFFu, alivec);
                if (lane == 0) alv[p + wid] = wb_;
                __syncthreads();      // orders alv (and cbox gather) for all

                // constant-latency winner find (1 LDS + 2 ballots + shfl per warp)
                unsigned x = (lane < 16) ? alv[p + lane] : 0u;
                unsigned ww = __ballot_sync(0xFFFFFFFFu, x != 0u);
                if (!ww) break;       // window exhausted (uniform decision)
                int wf = __ffs(ww) - 1;
                unsigned aw = __shfl_sync(0xFFFFFFFFu, x, wf);
                int ts = wf * 32 + (__ffs(aw) - 1);

                float4 wbx = cbox[ts];     // broadcast LDS
                float  wav = carea[ts];
                if (tid == ts) {
                    boxes_out[na * 4 + 0] = wbx.x;
                    boxes_out[na * 4 + 1] = wbx.y;
                    boxes_out[na * 4 + 2] = wbx.z;
                    boxes_out[na * 4 + 3] = wbx.w;
                    cls_out[na] = ccls[ts];
                    sco_out[na] = unmapf((unsigned)(ckey[ts] >> 32));
                    accb[na] = wbx;
                    acca[na] = wav;
                    alivec = false;        // winner consumed
                } else if (alivec) {
                    if (sup_test(wbx, wav, mycb, myca)) alivec = false;  // registers
                }
                na++;
            }
            __syncthreads();   // accb/acca visible before next window's pre-test
        }
        hi = lo;
        cumHi = loCum;
    }

    // --- pad remaining outputs with zeros; write num_det ---
    for (int t = na * 4 + tid; t < MAXDET * 4; t += NT) boxes_out[t] = 0.f;
    for (int t = na + tid; t < MAXDET; t += NT) { cls_out[t] = 0.f; sco_out[t] = 0.f; }
    if (tid == 0) *nd_out = (float)na;
}

extern "C" void kernel_launch(void* const* d_in, const int* in_sizes, int n_in,
                              void* d_out, int out_size)
{
    (void)in_sizes; (void)n_in; (void)out_size;
    const float* in = (const float*)d_in[0];
    float* out = (float*)d_out;
    cudaFuncSetAttribute(nms_kernel,
                         cudaFuncAttributeMaxDynamicSharedMemorySize, SMEM_TOTAL);
    decode_kernel<<<dim3(4, NIMG), NT>>>(in);
    nms_kernel<<<NIMG, NT, SMEM_TOTAL>>>(out);
}

// round 16
// speedup vs baseline: 5.9633x; 1.0361x over previous
#include <cuda_runtime.h>

#define NIMG    64
#define CH      36
#define NCLS    32
#define ANCH    8400
#define NT      512
#define MAXDET  100
#define CONF_T  0.25f
#define IOU_T   0.45f
#define WCAP    512
#define SLOTS   17            // ceil(8400/512) keys per thread, in registers

typedef unsigned long long u64;

// ---------------- global scratch (static __device__: allowed) ----------------
__device__ u64    g_key[NIMG][ANCH];
__device__ float4 g_box[NIMG][ANCH];
__device__ float  g_area[NIMG][ANCH];
__device__ float  g_cls[NIMG][ANCH];

static __device__ __forceinline__ unsigned mapf(float f) {
    unsigned u = __float_as_uint(f);
    return (u & 0x80000000u) ? ~u : (u | 0x80000000u);
}
static __device__ __forceinline__ float unmapf(unsigned u) {
    return __uint_as_float((u & 0x80000000u) ? (u ^ 0x80000000u) : ~u);
}

// exact-decision IoU > IOU_T test (guard-banded FMA, __fdiv_rn only in band)
static __device__ __forceinline__ bool sup_test(float4 w, float wa, float4 b, float ba) {
    float yy1 = fmaxf(w.x, b.x), xx1 = fmaxf(w.y, b.y);
    float yy2 = fminf(w.z, b.z), xx2 = fminf(w.w, b.w);
    float dy = fmaxf(__fsub_rn(yy2, yy1), 0.f);
    float dx = fmaxf(__fsub_rn(xx2, xx1), 0.f);
    float inter = __fmul_rn(dy, dx);
    float uni = __fsub_rn(__fadd_rn(wa, ba), inter);
    float t   = __fmaf_rn(-IOU_T, uni, inter);
    float bnd = 3e-7f * uni;
    if (t > bnd)  return true;
    if (t < -bnd) return false;
    return (uni > 0.f) && (__fdiv_rn(inter, uni) > IOU_T);
}

// ---------------- kernel 1: decode (bandwidth-bound, 256 CTAs) ----------------
__global__ __launch_bounds__(NT)
void decode_kernel(const float* __restrict__ in)
{
    const int img = blockIdx.y;
    const int chk = blockIdx.x;          // 4 chunks of 2100 anchors
    const float* base = in + (size_t)img * CH * ANCH;
    const int lo = chk * 2100;

    for (int a = lo + threadIdx.x; a < lo + 2100; a += NT) {
        float xc = base[a];
        float yc = base[ANCH + a];
        float w  = base[2 * ANCH + a];
        float h  = base[3 * ANCH + a];
        float best = base[4 * ANCH + a];
        int bc = 0;
        #pragma unroll
        for (int c = 1; c < NCLS; c++) {
            float v = base[(4 + c) * ANCH + a];
            if (v > best) { best = v; bc = c; }   // first-max == jnp.argmax
        }
        float y1 = fminf(fmaxf(yc - 0.5f * h, 0.f), 1.f);
        float x1 = fminf(fmaxf(xc - 0.5f * w, 0.f), 1.f);
        float y2 = fminf(fmaxf(yc + 0.5f * h, 0.f), 1.f);
        float x2 = fminf(fmaxf(xc + 0.5f * w, 0.f), 1.f);
        float area = __fmul_rn(__fsub_rn(y2, y1), __fsub_rn(x2, x1));
        u64 key = 0ull;
        if (best >= CONF_T)
            key = ((u64)mapf(best) << 32) | (unsigned)(0xFFFFFF - a);
        g_key[img][a]  = key;
        g_box[img][a]  = make_float4(y1, x1, y2, x2);
        g_area[img][a] = area;
        g_cls[img][a]  = (float)bc;
    }
}

// -------- kernel 2: register pivot-search + sort + segment-pipelined NMS ------
// SMEM layout (bytes) — tiny now
#define OFF_CKEY   0          // u64[512]    = 4096 (compaction target + sort scratch)
#define OFF_ACCB   4096       // float4[100] = 1600
#define OFF_ACCA   5696       // f32[100]    = 400
#define OFF_PART   6096       // u32[2][16]  = 128
#define OFF_MISC   6224       // u32[8]      = 32
#define SMEM_TOTAL 6272

__global__ __launch_bounds__(NT, 1)
void nms_kernel(float* __restrict__ out)
{
    extern __shared__ char smem[];
    u64*      ckey = (u64*)(smem + OFF_CKEY);
    float4*   accb = (float4*)(smem + OFF_ACCB);
    float*    acca = (float*)(smem + OFF_ACCA);
    unsigned* part = (unsigned*)(smem + OFF_PART);
    unsigned* misc = (unsigned*)(smem + OFF_MISC);

    const int tid  = threadIdx.x;
    const int img  = blockIdx.x;
    const int wid  = tid >> 5;
    const int lane = tid & 31;

    float* boxes_out = out + (size_t)img * MAXDET * 4;
    float* cls_out   = out + (size_t)NIMG * MAXDET * 4 + (size_t)img * MAXDET;
    float* sco_out   = out + (size_t)NIMG * MAXDET * 5 + (size_t)img * MAXDET;
    float* nd_out    = out + (size_t)NIMG * MAXDET * 6 + img;

    // --- keys live in registers (constant-indexed unrolled array) ---
    u64 kreg[SLOTS];
    #pragma unroll
    for (int s = 0; s < SLOTS; s++) {
        int i = tid + s * NT;
        kreg[s] = (i < ANCH) ? g_key[img][i] : 0ull;
    }

    int pc = 0;   // parity counter for 'part' double-buffering (uniform)

    // block-wide count of keys in (piv, up]; one barrier per call
    auto blockCount = [&](u64 piv, u64 up) -> int {
        unsigned c = 0;
        #pragma unroll
        for (int s = 0; s < SLOTS; s++)
            c += (kreg[s] > piv && kreg[s] <= up) ? 1u : 0u;
        #pragma unroll
        for (int off = 16; off >= 1; off >>= 1)
            c += __shfl_xor_sync(0xFFFFFFFFu, c, off);
        if (lane == 0) part[(pc & 1) * 16 + wid] = c;
        __syncthreads();
        unsigned tot = 0;
        #pragma unroll
        for (int w2 = 0; w2 < 16; w2++) tot += part[(pc & 1) * 16 + w2];
        pc++;
        return (int)tot;
    };

    int remaining = blockCount(0ull, ~0ull);

    int na = 0;
    u64 upper = ~0ull;

    while (na < MAXDET && remaining > 0) {
        // --- binary search full-u64 pivot: window = {k : pivot < k <= upper} ---
        u64 pivot; int wcount;
        if (remaining <= WCAP) {
            pivot = 0ull; wcount = remaining;
        } else {
            u64 blo = 0ull, bhi = upper; int bc = 0;
            // keys unique (index in low bits) => count steps by 1 => search
            // provably exits with bc in [256,512] (collapse gives exactly 512)
            #pragma unroll 1
            for (int itb = 0; itb < 60; itb++) {
                if (bhi - blo <= 1ull) break;
                u64 mid = blo + ((bhi - blo) >> 1);
                int c = blockCount(mid, upper);
                if (c > WCAP) blo = mid;
                else { bhi = mid; bc = c; if (c >= 256) break; }
            }
            pivot = bhi; wcount = bc;
        }
        (void)wcount;

        // --- compact window keys into ckey (unordered) ---
        if (tid == 0) misc[0] = 0;
        __syncthreads();
        #pragma unroll
        for (int s = 0; s < SLOTS; s++) {
            u64 k = kreg[s];
            bool pred = (k > pivot) && (k <= upper);
            unsigned act = __ballot_sync(0xFFFFFFFFu, pred);
            if (act) {
                int leader = __ffs(act) - 1;
                unsigned basep = 0;
                if (lane == leader) basep = atomicAdd(&misc[0], (unsigned)__popc(act));
                basep = __shfl_sync(0xFFFFFFFFu, basep, leader);
                if (pred) ckey[basep + __popc(act & ((1u << lane) - 1))] = k;
            }
        }
        __syncthreads();
        int selCount = (int)misc[0];
        if (selCount > WCAP) selCount = WCAP;   // safety (should equal wcount)

        if (selCount > 0) {
            u64 v = (tid < selCount) ? ckey[tid] : 0ull;
            __syncthreads();   // all initial reads done before sort overwrites ckey

            // --- bitonic sort, 1 key/thread, descending; shuffles for j<32 ---
            #pragma unroll
            for (int k = 2; k <= NT; k <<= 1) {
                for (int j = k >> 1; j > 0; j >>= 1) {
                    u64 o;
                    if (j >= 32) {
                        ckey[tid] = v;
                        __syncthreads();
                        o = ckey[tid ^ j];
                        __syncthreads();
                    } else {
                        o = __shfl_xor_sync(0xFFFFFFFFu, v, j);
                    }
                    bool dirDesc = ((tid & k) == 0);
                    bool lower   = ((tid & j) == 0);
                    bool takeMax = (dirDesc == lower);
                    v = takeMax ? (v > o ? v : o) : (v < o ? v : o);
                }
            }

            // --- gather my candidate into registers + pre-test vs accepted ---
            float4 mycb = make_float4(0.f, 0.f, 0.f, 0.f);
            float  myca = 0.f, mycl = 0.f;
            bool alivec = false;
            if (tid < selCount) {
                int idx = 0xFFFFFF - (int)(unsigned)(v & 0xFFFFFFu);
                mycb = g_box[img][idx];
                myca = g_area[img][idx];
                mycl = g_cls[img][idx];
                alivec = true;
                for (int a2 = 0; a2 < na; a2++) {
                    if (sup_test(accb[a2], acca[a2], mycb, myca)) { alivec = false; break; }
                }
            }

            // --- segment-pipelined stepping: 16 barriers, registers only ---
            for (int seg = 0; seg < 16 && na < MAXDET; seg++) {
                if (wid == seg) {
                    int lna = na;
                    unsigned alive = __ballot_sync(0xFFFFFFFFu, alivec);
                    while (alive && lna < MAXDET) {
                        int l = __ffs(alive) - 1;
                        float wx = __shfl_sync(0xFFFFFFFFu, mycb.x, l);
                        float wy = __shfl_sync(0xFFFFFFFFu, mycb.y, l);
                        float wz = __shfl_sync(0xFFFFFFFFu, mycb.z, l);
                        float wq = __shfl_sync(0xFFFFFFFFu, mycb.w, l);
                        float wa = __shfl_sync(0xFFFFFFFFu, myca, l);
                        if (lane == l) {
                            boxes_out[lna * 4 + 0] = mycb.x;
                            boxes_out[lna * 4 + 1] = mycb.y;
                            boxes_out[lna * 4 + 2] = mycb.z;
                            boxes_out[lna * 4 + 3] = mycb.w;
                            cls_out[lna] = mycl;
                            sco_out[lna] = unmapf((unsigned)(v >> 32));
                            accb[lna] = mycb;
                            acca[lna] = myca;
                            alivec = false;                    // consumed
                        } else if (alivec) {
                            float4 wbx = make_float4(wx, wy, wz, wq);
                            if (sup_test(wbx, wa, mycb, myca)) alivec = false;
                        }
                        lna++;
                        alive = __ballot_sync(0xFFFFFFFFu, alivec);
                    }
                    if (lane == 0) misc[2 + (seg & 1)] = (unsigned)lna;
                }
                __syncthreads();
                int newNa = (int)misc[2 + (seg & 1)];
                if (wid > seg && alivec) {
                    for (int a2 = na; a2 < newNa; a2++) {
                        if (sup_test(accb[a2], acca[a2], mycb, myca)) { alivec = false; break; }
                    }
                }
                na = newNa;
            }
            __syncthreads();   // accb/misc stable before next window
        }
        upper = pivot;
        remaining -= selCount;
    }

    // --- pad remaining outputs with zeros; write num_det ---
    for (int t = na * 4 + tid; t < MAXDET * 4; t += NT) boxes_out[t] = 0.f;
    for (int t = na + tid; t < MAXDET; t += NT) { cls_out[t] = 0.f; sco_out[t] = 0.f; }
    if (tid == 0) *nd_out = (float)na;
}

extern "C" void kernel_launch(void* const* d_in, const int* in_sizes, int n_in,
                              void* d_out, int out_size)
{
    (void)in_sizes; (void)n_in; (void)out_size;
    const float* in = (const float*)d_in[0];
    float* out = (float*)d_out;
    cudaFuncSetAttribute(nms_kernel,
                         cudaFuncAttributeMaxDynamicSharedMemorySize, SMEM_TOTAL);
    decode_kernel<<<dim3(4, NIMG), NT>>>(in);
    nms_kernel<<<NIMG, NT, SMEM_TOTAL>>>(out);
}